// round 12
// baseline (speedup 1.0000x reference)
#include <cuda_runtime.h>
#include <math.h>

// Feature map (1, 50, 75, 512) fp32, rois (1000, 4), img_size (2,) int32.
// Output: (1000, 7, 7, 512) fp32 = crop_and_resize(14x14 bilinear) + 2x2 maxpool.
// Design (frozen pending first successful bench):
//  - grid (7,7,1000), 128 threads; one CTA per output cell, thread = 4 channels.
//  - blockIdx-uniform coordinate math (uniform datapath, no barrier).
//  - 16 independent LDG.E.128 front-batched (MLP=16) against L2-resident fmap.
//  - bilinear lerp in the reference's exact op order; masked; 2x2 max; float4 store.
#define FM_H 50
#define FM_W 75
#define FM_C 512
#define POOLN 7
#define CVEC (FM_C / 4)   // 128 float4 per pixel

__global__ __launch_bounds__(CVEC)
void roi_pool_kernel(const float4* __restrict__ fm,
                     const float*  __restrict__ rois,
                     const int*    __restrict__ img_size,
                     float4*       __restrict__ out)
{
    const int px = blockIdx.x;            // 0..6
    const int py = blockIdx.y;            // 0..6
    const int n  = blockIdx.z;            // 0..999
    const int t  = threadIdx.x;           // channel group 0..127

    const float fh = (float)(FM_H - 1);   // 49
    const float fw = (float)(FM_W - 1);   // 74

    const float inv_h = 1.0f / ((float)__ldg(&img_size[0]) - 1.0f);
    const float inv_w = 1.0f / ((float)__ldg(&img_size[1]) - 1.0f);

    const float rx1 = __ldg(&rois[n * 4 + 0]);
    const float ry1 = __ldg(&rois[n * 4 + 1]);
    const float rx2 = __ldg(&rois[n * 4 + 2]);
    const float ry2 = __ldg(&rois[n * 4 + 3]);

    // Normalized box, same op order as the reference
    const float y1 = ry1 * inv_h;
    const float x1 = rx1 * inv_w;
    const float y2 = ry2 * inv_h;
    const float x2 = rx2 * inv_w;

    const float sy = (y2 - y1) * fh / 13.0f;   // per-sample-step increments
    const float sx = (x2 - x1) * fw / 13.0f;
    const float by = y1 * fh;
    const float bx = x1 * fw;

    // ---- Phase 1: sample coords / weights / addresses (blockIdx-uniform) ----
    int   p00[4], p01[4], p10[4], p11[4];
    float wgx[4], wgy[4];
    bool  vld[4];

#pragma unroll
    for (int s = 0; s < 4; s++) {
        const int dy = s >> 1, dx = s & 1;
        const float ysv = by + (float)(py * 2 + dy) * sy;
        const float xsv = bx + (float)(px * 2 + dx) * sx;

        vld[s] = (ysv >= 0.0f) & (ysv <= fh) & (xsv >= 0.0f) & (xsv <= fw);

        const float yf = floorf(ysv);
        const float xf = floorf(xsv);
        wgy[s] = ysv - yf;
        wgx[s] = xsv - xf;

        int y0 = min(max((int)yf, 0), FM_H - 1);
        int x0 = min(max((int)xf, 0), FM_W - 1);
        const int y1i = min(y0 + 1, FM_H - 1);
        const int x1i = min(x0 + 1, FM_W - 1);

        p00[s] = (y0  * FM_W + x0 ) * CVEC + t;
        p01[s] = (y0  * FM_W + x1i) * CVEC + t;
        p10[s] = (y1i * FM_W + x0 ) * CVEC + t;
        p11[s] = (y1i * FM_W + x1i) * CVEC + t;
    }

    // ---- Phase 2: issue all 16 independent texel loads (front batch, MLP=16) ----
    float4 tl[4], tr[4], bl[4], br[4];
#pragma unroll
    for (int s = 0; s < 4; s++) {
        tl[s] = __ldg(&fm[p00[s]]);
        tr[s] = __ldg(&fm[p01[s]]);
        bl[s] = __ldg(&fm[p10[s]]);
        br[s] = __ldg(&fm[p11[s]]);
    }

    // ---- Phase 3: bilinear lerp (reference op order) + masked max ----
    float4 acc;
    acc.x = -INFINITY; acc.y = -INFINITY; acc.z = -INFINITY; acc.w = -INFINITY;

#pragma unroll
    for (int s = 0; s < 4; s++) {
        const float wx = wgx[s];
        const float wy = wgy[s];
        float4 v;
        {
            float top, bot;
            top = tl[s].x + wx * (tr[s].x - tl[s].x);
            bot = bl[s].x + wx * (br[s].x - bl[s].x);
            v.x = top + wy * (bot - top);
            top = tl[s].y + wx * (tr[s].y - tl[s].y);
            bot = bl[s].y + wx * (br[s].y - bl[s].y);
            v.y = top + wy * (bot - top);
            top = tl[s].z + wx * (tr[s].z - tl[s].z);
            bot = bl[s].z + wx * (br[s].z - bl[s].z);
            v.z = top + wy * (bot - top);
            top = tl[s].w + wx * (tr[s].w - tl[s].w);
            bot = bl[s].w + wx * (br[s].w - bl[s].w);
            v.w = top + wy * (bot - top);
        }
        if (!vld[s]) { v.x = 0.0f; v.y = 0.0f; v.z = 0.0f; v.w = 0.0f; }

        acc.x = fmaxf(acc.x, v.x);
        acc.y = fmaxf(acc.y, v.y);
        acc.z = fmaxf(acc.z, v.z);
        acc.w = fmaxf(acc.w, v.w);
    }

    const size_t ob = ((size_t)n * (POOLN * POOLN) + py * POOLN + px) * CVEC + t;
    out[ob] = acc;
}

extern "C" void kernel_launch(void* const* d_in, const int* in_sizes, int n_in,
                              void* d_out, int out_size)
{
    const float4* fm       = (const float4*)d_in[0];   // (1,50,75,512) fp32
    const float*  rois     = (const float*)d_in[1];    // (1000,4) fp32
    const int*    img_size = (const int*)d_in[2];      // (2,) int32
    float4*       out      = (float4*)d_out;           // (1000,7,7,512) fp32

    const int n_rois = in_sizes[1] / 4;
    dim3 grid(POOLN, POOLN, n_rois);                   // (7,7,1000)
    roi_pool_kernel<<<grid, CVEC>>>(fm, rois, img_size, out);
}

// round 15
// speedup vs baseline: 1.2355x; 1.2355x over previous
#include <cuda_runtime.h>
#include <math.h>

// Feature map (1, 50, 75, 512) fp32, rois (1000, 4), img_size (2,) int32.
// Output: (1000, 7, 7, 512) fp32 = crop_and_resize(14x14 bilinear) + 2x2 maxpool.
// R12 design: one CTA per (ROI, output row): grid (7, 1000), 128 threads.
//  - y-samples + ROI math amortized over the 7 px cells (loop).
//  - weight-form bilinear (FMUL + 3 FFMA per channel) with validity folded
//    into the scalar weights (exactly reproduces where(valid, lerp, 0)).
//  - 16 independent LDG.E.128 per cell, coalesced float4 stores.
#define FM_H 50
#define FM_W 75
#define FM_C 512
#define POOLN 7
#define CVEC (FM_C / 4)   // 128 float4 per pixel

__global__ __launch_bounds__(CVEC)
void roi_pool_row_kernel(const float4* __restrict__ fm,
                         const float*  __restrict__ rois,
                         const int*    __restrict__ img_size,
                         float4*       __restrict__ out)
{
    const int py = blockIdx.x;            // 0..6  output row
    const int n  = blockIdx.y;            // 0..999 ROI
    const int t  = threadIdx.x;           // channel group 0..127

    const float fh = (float)(FM_H - 1);   // 49
    const float fw = (float)(FM_W - 1);   // 74

    const float inv_h = 1.0f / ((float)__ldg(&img_size[0]) - 1.0f);
    const float inv_w = 1.0f / ((float)__ldg(&img_size[1]) - 1.0f);

    const float4 roi = __ldg((const float4*)(rois + n * 4)); // x1,y1,x2,y2

    // Normalized box, same op order as the reference
    const float y1 = roi.y * inv_h;
    const float x1 = roi.x * inv_w;
    const float y2 = roi.w * inv_h;
    const float x2 = roi.z * inv_w;

    const float sy = (y2 - y1) * fh / 13.0f;
    const float sx = (x2 - x1) * fw / 13.0f;
    const float by = y1 * fh;
    const float bx = x1 * fw;

    // ---- y-samples for this output row (shared across all 7 px cells) ----
    float wyv[2], omyv[2];
    int   yb[2], ydo[2];
#pragma unroll
    for (int j = 0; j < 2; j++) {
        const float ysv = by + (float)(py * 2 + j) * sy;
        const bool  v   = (ysv >= 0.0f) & (ysv <= fh);
        const float yf  = floorf(ysv);
        const float wy  = ysv - yf;
        int y0 = min(max((int)yf, 0), FM_H - 1);
        const int y1i = min(y0 + 1, FM_H - 1);
        wyv [j] = v ? wy         : 0.0f;   // fold y-validity into weights
        omyv[j] = v ? 1.0f - wy  : 0.0f;
        yb  [j] = y0 * FM_W;
        ydo [j] = (y1i - y0) * FM_W;
    }

    size_t obase = ((size_t)n * (POOLN * POOLN) + py * POOLN) * CVEC + t;

    for (int px = 0; px < POOLN; px++) {
        // ---- x-samples for this cell ----
        float wxv[2], omxv[2];
        int   xb[2], xdo[2];
#pragma unroll
        for (int i = 0; i < 2; i++) {
            const float xsv = bx + (float)(px * 2 + i) * sx;
            const bool  v   = (xsv >= 0.0f) & (xsv <= fw);
            const float xf  = floorf(xsv);
            const float wx  = xsv - xf;
            int x0 = min(max((int)xf, 0), FM_W - 1);
            const int x1i = min(x0 + 1, FM_W - 1);
            wxv [i] = v ? wx        : 0.0f;   // fold x-validity into weights
            omxv[i] = v ? 1.0f - wx : 0.0f;
            xb  [i] = x0;
            xdo [i] = x1i - x0;
        }

        // ---- front-batch the 16 independent texel loads ----
        float4 tl[4], tr[4], bl[4], br[4];
#pragma unroll
        for (int s = 0; s < 4; s++) {
            const int j = s >> 1, i = s & 1;
            const int p00 = yb[j] + xb[i];
            const int p01 = p00 + xdo[i];
            const int p10 = p00 + ydo[j];
            const int p11 = p10 + xdo[i];
            tl[s] = __ldg(&fm[p00 * CVEC + t]);
            tr[s] = __ldg(&fm[p01 * CVEC + t]);
            bl[s] = __ldg(&fm[p10 * CVEC + t]);
            br[s] = __ldg(&fm[p11 * CVEC + t]);
        }

        // ---- weight-form bilinear + max ----
        float4 acc;
        acc.x = -INFINITY; acc.y = -INFINITY; acc.z = -INFINITY; acc.w = -INFINITY;
#pragma unroll
        for (int s = 0; s < 4; s++) {
            const int j = s >> 1, i = s & 1;
            const float w00 = omyv[j] * omxv[i];
            const float w01 = omyv[j] * wxv [i];
            const float w10 = wyv [j] * omxv[i];
            const float w11 = wyv [j] * wxv [i];
            float4 v;
            v.x = w00 * tl[s].x + w01 * tr[s].x + w10 * bl[s].x + w11 * br[s].x;
            v.y = w00 * tl[s].y + w01 * tr[s].y + w10 * bl[s].y + w11 * br[s].y;
            v.z = w00 * tl[s].z + w01 * tr[s].z + w10 * bl[s].z + w11 * br[s].z;
            v.w = w00 * tl[s].w + w01 * tr[s].w + w10 * bl[s].w + w11 * br[s].w;
            acc.x = fmaxf(acc.x, v.x);
            acc.y = fmaxf(acc.y, v.y);
            acc.z = fmaxf(acc.z, v.z);
            acc.w = fmaxf(acc.w, v.w);
        }

        out[obase + (size_t)px * CVEC] = acc;
    }
}

extern "C" void kernel_launch(void* const* d_in, const int* in_sizes, int n_in,
                              void* d_out, int out_size)
{
    const float4* fm       = (const float4*)d_in[0];   // (1,50,75,512) fp32
    const float*  rois     = (const float*)d_in[1];    // (1000,4) fp32
    const int*    img_size = (const int*)d_in[2];      // (2,) int32
    float4*       out      = (float4*)d_out;           // (1000,7,7,512) fp32

    const int n_rois = in_sizes[1] / 4;
    dim3 grid(POOLN, n_rois);                          // (7, 1000)
    roi_pool_row_kernel<<<grid, CVEC>>>(fm, rois, img_size, out);
}